// round 4
// baseline (speedup 1.0000x reference)
#include <cuda_runtime.h>
#include <cuda_bf16.h>

#define GEPS 1e-8f
constexpr int BS    = 256;
constexpr int ITEMS = 2;
constexpr int PTS   = BS * ITEMS;   // points per block = 512

__device__ __forceinline__ void cov_from_q(
    float4 qv, float sa, float sb, float sc, float* __restrict__ o /* 9 floats */)
{
    float w = qv.x, x = qv.y, y = qv.z, z = qv.w;
    float inv = rsqrtf(w * w + x * x + y * y + z * z);
    w *= inv; x *= inv; y *= inv; z *= inv;

    const float r00 = 1.f - 2.f * (y * y + z * z);
    const float r01 = 2.f * (x * y - w * z);
    const float r02 = 2.f * (x * z + w * y);
    const float r10 = 2.f * (x * y + w * z);
    const float r11 = 1.f - 2.f * (x * x + z * z);
    const float r12 = 2.f * (y * z - w * x);
    const float r20 = 2.f * (x * z - w * y);
    const float r21 = 2.f * (y * z + w * x);
    const float r22 = 1.f - 2.f * (x * x + y * y);

    sa = fabsf(sa) + GEPS;
    sb = fabsf(sb) + GEPS;
    sc = fabsf(sc) + GEPS;
    const float a = sa * sa, b = sb * sb, c = sc * sc;

    const float m00 = r00 * r00 * a + r01 * r01 * b + r02 * r02 * c;
    const float m01 = r00 * r10 * a + r01 * r11 * b + r02 * r12 * c;
    const float m02 = r00 * r20 * a + r01 * r21 * b + r02 * r22 * c;
    const float m11 = r10 * r10 * a + r11 * r11 * b + r12 * r12 * c;
    const float m12 = r10 * r20 * a + r11 * r21 * b + r12 * r22 * c;
    const float m22 = r20 * r20 * a + r21 * r21 * b + r22 * r22 * c;

    o[0] = m00; o[1] = m01; o[2] = m02;
    o[3] = m01; o[4] = m11; o[5] = m12;
    o[6] = m02; o[7] = m12; o[8] = m22;
}

__global__ __launch_bounds__(BS) void gaussians_cov_kernel(
    const float4* __restrict__ q,     // [N] float4 (w,x,y,z)
    const float*  __restrict__ s,     // [N*3]
    float*        __restrict__ out,   // [N*9]
    int N)
{
    __shared__ float ssm[PTS * 3];   // 6 KB staged scales
    __shared__ float osm[PTS * 9];   // 18 KB staged outputs

    const int base = blockIdx.x * PTS;
    const int tid  = threadIdx.x;
    const bool full = (base + PTS) <= N;

    if (full) {
        // ---- front-batch ALL global loads (maximize MLP) ----
        // q loads: 2 independent float4s per thread
        float4 qv0 = __ldcs(&q[base + tid]);
        float4 qv1 = __ldcs(&q[base + BS + tid]);

        // scale slab: PTS*3 = 1536 floats = 384 float4, 1.5 per thread
        const float4* s4   = reinterpret_cast<const float4*>(s) + (size_t)base * 3 / 4;
        float4*       ssm4 = reinterpret_cast<float4*>(ssm);
        ssm4[tid] = __ldcs(&s4[tid]);
        if (tid < PTS * 3 / 4 - BS) ssm4[BS + tid] = __ldcs(&s4[BS + tid]);
        __syncthreads();

        // ---- compute both points, stage to smem ----
        const int p0 = tid, p1 = BS + tid;
        cov_from_q(qv0, ssm[p0 * 3 + 0], ssm[p0 * 3 + 1], ssm[p0 * 3 + 2], osm + p0 * 9);
        cov_from_q(qv1, ssm[p1 * 3 + 0], ssm[p1 * 3 + 1], ssm[p1 * 3 + 2], osm + p1 * 9);
        __syncthreads();

        // ---- cooperative coalesced streaming store ----
        // PTS*9 = 4608 floats = 1152 float4, 4.5 per thread
        float4*       out4 = reinterpret_cast<float4*>(out) + (size_t)base * 9 / 4;
        const float4* osm4 = reinterpret_cast<const float4*>(osm);
        #pragma unroll
        for (int i = tid; i < PTS * 9 / 4; i += BS) __stcs(&out4[i], osm4[i]);
    } else {
        // tail block: scalar guarded path
        #pragma unroll
        for (int k = 0; k < ITEMS; ++k) {
            const int n = base + k * BS + tid;
            if (n < N) {
                float4 qv = q[n];
                float obuf[9];
                cov_from_q(qv, s[n * 3 + 0], s[n * 3 + 1], s[n * 3 + 2], obuf);
                float* o = out + (size_t)n * 9;
                #pragma unroll
                for (int j = 0; j < 9; ++j) o[j] = obuf[j];
            }
        }
    }
}

extern "C" void kernel_launch(void* const* d_in, const int* in_sizes, int n_in,
                              void* d_out, int out_size) {
    const float4* q = (const float4*)d_in[0];   // quaternion [N,4]
    const float*  s = (const float*)d_in[1];    // scale [N,3]
    float* out = (float*)d_out;                 // [N,3,3]
    const int N = in_sizes[0] / 4;

    const int grid = (N + PTS - 1) / PTS;
    gaussians_cov_kernel<<<grid, BS>>>(q, s, out, N);
}

// round 5
// speedup vs baseline: 1.1544x; 1.1544x over previous
#include <cuda_runtime.h>
#include <cuda_bf16.h>

#define GEPS 1e-8f
constexpr int BS    = 256;         // 8 warps
constexpr int WARPS = BS / 32;

__device__ __forceinline__ void cov_from_q(
    float4 qv, float sa, float sb, float sc, float* __restrict__ o /* 9 floats */)
{
    float w = qv.x, x = qv.y, y = qv.z, z = qv.w;
    float inv = rsqrtf(w * w + x * x + y * y + z * z);
    w *= inv; x *= inv; y *= inv; z *= inv;

    const float r00 = 1.f - 2.f * (y * y + z * z);
    const float r01 = 2.f * (x * y - w * z);
    const float r02 = 2.f * (x * z + w * y);
    const float r10 = 2.f * (x * y + w * z);
    const float r11 = 1.f - 2.f * (x * x + z * z);
    const float r12 = 2.f * (y * z - w * x);
    const float r20 = 2.f * (x * z - w * y);
    const float r21 = 2.f * (y * z + w * x);
    const float r22 = 1.f - 2.f * (x * x + y * y);

    sa = fabsf(sa) + GEPS;
    sb = fabsf(sb) + GEPS;
    sc = fabsf(sc) + GEPS;
    const float a = sa * sa, b = sb * sb, c = sc * sc;

    const float m00 = r00 * r00 * a + r01 * r01 * b + r02 * r02 * c;
    const float m01 = r00 * r10 * a + r01 * r11 * b + r02 * r12 * c;
    const float m02 = r00 * r20 * a + r01 * r21 * b + r02 * r22 * c;
    const float m11 = r10 * r10 * a + r11 * r11 * b + r12 * r12 * c;
    const float m12 = r10 * r20 * a + r11 * r21 * b + r12 * r22 * c;
    const float m22 = r20 * r20 * a + r21 * r21 * b + r22 * r22 * c;

    o[0] = m00; o[1] = m01; o[2] = m02;
    o[3] = m01; o[4] = m11; o[5] = m12;
    o[6] = m02; o[7] = m12; o[8] = m22;
}

__global__ __launch_bounds__(BS) void gaussians_cov_kernel(
    const float4* __restrict__ q,     // [N] float4 (w,x,y,z)
    const float*  __restrict__ s,     // [N*3]
    float*        __restrict__ out,   // [N*9]
    int N)
{
    // warp-private staging: no block-wide barriers anywhere on the hot path
    __shared__ float ssm[WARPS][32 * 3];   // 8 * 384 B  = 3 KB
    __shared__ float osm[WARPS][32 * 9];   // 8 * 1152 B = 9 KB

    const int tid   = threadIdx.x;
    const int wid   = tid >> 5;
    const int lane  = tid & 31;
    const int base  = blockIdx.x * BS + wid * 32;   // this warp's 32 points
    const bool full = (base + 32) <= N;

    if (full) {
        // ---- warp-cooperative loads ----
        float4 qv = q[base + lane];                       // coalesced 512B

        // scale slab for this warp: 96 floats = 24 float4 (16B-aligned: base*3*4B = 384*k)
        const float4* s4   = reinterpret_cast<const float4*>(s) + (size_t)base * 3 / 4;
        float4* ssm4 = reinterpret_cast<float4*>(ssm[wid]);
        if (lane < 24) ssm4[lane] = s4[lane];
        __syncwarp();

        // ---- compute, stage to warp-private smem ----
        const float* sp = &ssm[wid][lane * 3];            // stride 3: conflict-free
        cov_from_q(qv, sp[0], sp[1], sp[2], &osm[wid][lane * 9]);  // stride 9: conflict-free
        __syncwarp();

        // ---- warp-cooperative coalesced store: 288 floats = 72 float4 ----
        float4*       out4 = reinterpret_cast<float4*>(out) + (size_t)base * 9 / 4;
        const float4* osm4 = reinterpret_cast<const float4*>(osm[wid]);
        out4[lane]      = osm4[lane];
        out4[32 + lane] = osm4[32 + lane];
        if (lane < 8) out4[64 + lane] = osm4[64 + lane];
    } else {
        const int n = base + lane;
        if (n < N) {
            float4 qv = q[n];
            float obuf[9];
            cov_from_q(qv, s[n * 3 + 0], s[n * 3 + 1], s[n * 3 + 2], obuf);
            float* o = out + (size_t)n * 9;
            #pragma unroll
            for (int j = 0; j < 9; ++j) o[j] = obuf[j];
        }
    }
}

extern "C" void kernel_launch(void* const* d_in, const int* in_sizes, int n_in,
                              void* d_out, int out_size) {
    const float4* q = (const float4*)d_in[0];   // quaternion [N,4]
    const float*  s = (const float*)d_in[1];    // scale [N,3]
    float* out = (float*)d_out;                 // [N,3,3]
    const int N = in_sizes[0] / 4;

    const int grid = (N + BS - 1) / BS;
    gaussians_cov_kernel<<<grid, BS>>>(q, s, out, N);
}